// round 3
// baseline (speedup 1.0000x reference)
#include <cuda_runtime.h>
#include <math.h>
#include <stdint.h>

#define D        2048
#define NEXP     64
#define TM       128
#define KC       32
#define NCHUNK   (D / KC)        // 64
#define STAGES   6
#define NTOK     16384
#define TAU      0.25f

#define APITCH   36                       // floats per A row (pad: banks 4g+tig distinct)
#define BPITCH   72                       // floats per B row (pad: banks 8t+g distinct)
#define A_BYTES  (TM * APITCH * 4)        // 18432
#define B_BYTES  (KC * BPITCH * 4)        // 9216
#define STAGE_BYTES (A_BYTES + B_BYTES)   // 27648
#define SMEM_TOTAL  (STAGES * STAGE_BYTES)

__device__ float g_enorm[NEXP * D];       // fp32 normalized experts (fixup path)
__device__ float g_enorm_t[D * NEXP];     // tf32-rounded, transposed [k][e] (gemm B)
__device__ float g_esum[NEXP];
__device__ int   g_flag_list[NTOK];
__device__ int   g_flag_count;

__device__ __forceinline__ void cp_async16(uint32_t dst, const void* src) {
    asm volatile("cp.async.cg.shared.global [%0], [%1], 16;"
                 :: "r"(dst), "l"(src) : "memory");
}
__device__ __forceinline__ void mma_tf32(float* c, float a0, float a1, float a2, float a3,
                                         float b0, float b1) {
    asm volatile(
        "mma.sync.aligned.m16n8k8.row.col.f32.tf32.tf32.f32 "
        "{%0,%1,%2,%3}, {%4,%5,%6,%7}, {%8,%9}, {%0,%1,%2,%3};"
        : "+f"(c[0]), "+f"(c[1]), "+f"(c[2]), "+f"(c[3])
        : "r"(__float_as_uint(a0)), "r"(__float_as_uint(a1)),
          "r"(__float_as_uint(a2)), "r"(__float_as_uint(a3)),
          "r"(__float_as_uint(b0)), "r"(__float_as_uint(b1)));
}
__device__ __forceinline__ void ins3(float v, int e, float& v1, int& i1,
                                     float& v2, int& i2, float& v3) {
    if (v > v1)      { v3 = v2; v2 = v1; i2 = i1; v1 = v; i1 = e; }
    else if (v > v2) { v3 = v2; v2 = v; i2 = e; }
    else if (v > v3) { v3 = v; }
}

__device__ __forceinline__ float block_reduce256(float v, float* red) {
    int tid = threadIdx.x;
    __syncthreads();
    #pragma unroll
    for (int o = 16; o > 0; o >>= 1) v += __shfl_xor_sync(0xffffffffu, v, o);
    if ((tid & 31) == 0) red[tid >> 5] = v;
    __syncthreads();
    float r = (tid < 8) ? red[tid] : 0.f;
    #pragma unroll
    for (int o = 4; o > 0; o >>= 1) r += __shfl_xor_sync(0xffffffffu, r, o);
    if (tid == 0) red[0] = r;
    __syncthreads();
    return red[0];
}

// ------------- kernel 1: normalize expert table (fp32 + tf32-transposed) -------------
__global__ __launch_bounds__(256) void normalize_experts(const float* __restrict__ emb) {
    __shared__ float red[8];
    const int e = blockIdx.x, tid = threadIdx.x;
    const float4* row = reinterpret_cast<const float4*>(emb + e * D);
    float4 v0 = row[tid];
    float4 v1 = row[tid + 256];
    float s  = v0.x + v0.y + v0.z + v0.w + v1.x + v1.y + v1.z + v1.w;
    float sq = v0.x*v0.x + v0.y*v0.y + v0.z*v0.z + v0.w*v0.w
             + v1.x*v1.x + v1.y*v1.y + v1.z*v1.z + v1.w*v1.w;
    s  = block_reduce256(s, red);
    sq = block_reduce256(sq, red);
    const float mu   = s * (1.f / D);
    const float var  = sq * (1.f / D) - mu * mu;
    const float rstd = rsqrtf(var + 1e-5f);

    float nv[8];
    nv[0] = (v0.x-mu)*rstd; nv[1] = (v0.y-mu)*rstd; nv[2] = (v0.z-mu)*rstd; nv[3] = (v0.w-mu)*rstd;
    nv[4] = (v1.x-mu)*rstd; nv[5] = (v1.y-mu)*rstd; nv[6] = (v1.z-mu)*rstd; nv[7] = (v1.w-mu)*rstd;

    float4* o = reinterpret_cast<float4*>(g_enorm + e * D);
    o[tid]       = make_float4(nv[0], nv[1], nv[2], nv[3]);
    o[tid + 256] = make_float4(nv[4], nv[5], nv[6], nv[7]);

    float ls = 0.f;
    #pragma unroll
    for (int i = 0; i < 4; i++) {
        int k0 = tid * 4 + i;
        int k1 = 1024 + tid * 4 + i;
        uint32_t r0, r1;                              // pre-round B to tf32 (RNA)
        asm("cvt.rna.tf32.f32 %0, %1;" : "=r"(r0) : "f"(nv[i]));
        asm("cvt.rna.tf32.f32 %0, %1;" : "=r"(r1) : "f"(nv[4 + i]));
        g_enorm_t[k0 * NEXP + e] = __uint_as_float(r0);
        g_enorm_t[k1 * NEXP + e] = __uint_as_float(r1);
        ls += nv[i] + nv[4 + i];
    }
    ls = block_reduce256(ls, red);
    if (tid == 0) g_esum[e] = ls;
}

// ------------- kernel 2: tf32 mma.sync GEMM + fused LN + top-2 -------------
__global__ __launch_bounds__(256, 1) void gemm_kernel(const float* __restrict__ x,
                                                      float* __restrict__ out, int half)
{
    extern __shared__ __align__(128) char smem[];
    float* sm = reinterpret_cast<float*>(smem);
    const uint32_t sb = (uint32_t)__cvta_generic_to_shared(smem);

    const int tid  = threadIdx.x;
    const int warp = tid >> 5;
    const int lane = tid & 31;
    const int g    = lane >> 2;
    const int tig  = lane & 3;
    const int m0   = blockIdx.x * TM;

    #define ISSUE_OPS(c) do {                                                   \
        int st_ = (c) % STAGES;                                                 \
        uint32_t base_ = sb + st_ * STAGE_BYTES;                                \
        _Pragma("unroll")                                                       \
        for (int i_ = 0; i_ < 4; i_++) {                                        \
            int idx_ = tid + i_ * 256;                                          \
            int row_ = idx_ >> 3, seg_ = idx_ & 7;                              \
            cp_async16(base_ + row_ * (APITCH * 4) + seg_ * 16,                 \
                       x + (size_t)(m0 + row_) * D + (c) * KC + seg_ * 4);      \
        }                                                                       \
        _Pragma("unroll")                                                       \
        for (int i_ = 0; i_ < 2; i_++) {                                        \
            int idx_ = tid + i_ * 256;                                          \
            int row_ = idx_ >> 4, seg_ = idx_ & 15;                             \
            cp_async16(base_ + A_BYTES + row_ * (BPITCH * 4) + seg_ * 16,       \
                       g_enorm_t + ((c) * KC + row_) * NEXP + seg_ * 4);        \
        }                                                                       \
    } while (0)

    #pragma unroll
    for (int c = 0; c < STAGES - 1; c++) {
        ISSUE_OPS(c);
        asm volatile("cp.async.commit_group;" ::: "memory");
    }

    float acc[32];
    #pragma unroll
    for (int i = 0; i < 32; i++) acc[i] = 0.f;
    float s_lo = 0.f, sq_lo = 0.f, s_hi = 0.f, sq_hi = 0.f;

    for (int c = 0; c < NCHUNK; c++) {
        asm volatile("cp.async.wait_group 4;" ::: "memory");
        __syncthreads();
        if (c + STAGES - 1 < NCHUNK) ISSUE_OPS(c + STAGES - 1);
        asm volatile("cp.async.commit_group;" ::: "memory");

        const int st = c % STAGES;
        const float* As = sm + (st * STAGE_BYTES >> 2);
        const float* Bs = As + (A_BYTES >> 2);
        const int alo = (warp * 16 + g) * APITCH;
        const int ahi = alo + 8 * APITCH;

        #pragma unroll
        for (int ks = 0; ks < 4; ks++) {
            const int k0 = ks * 8 + tig;
            float a0 = As[alo + k0];
            float a1 = As[ahi + k0];
            float a2 = As[alo + k0 + 4];
            float a3 = As[ahi + k0 + 4];
            s_lo += a0 + a2;  sq_lo += a0 * a0 + a2 * a2;
            s_hi += a1 + a3;  sq_hi += a1 * a1 + a3 * a3;
            #pragma unroll
            for (int nt = 0; nt < 8; nt++) {
                float b0 = Bs[k0 * BPITCH + nt * 8 + g];
                float b1 = Bs[(k0 + 4) * BPITCH + nt * 8 + g];
                mma_tf32(acc + nt * 4, a0, a1, a2, a3, b0, b1);
            }
        }
    }
    asm volatile("cp.async.wait_all;" ::: "memory");

    // stats: reduce over the 4-lane k-groups (lanes differ only in tig)
    #pragma unroll
    for (int o = 1; o <= 2; o <<= 1) {
        s_lo  += __shfl_xor_sync(0xffffffffu, s_lo,  o);
        sq_lo += __shfl_xor_sync(0xffffffffu, sq_lo, o);
        s_hi  += __shfl_xor_sync(0xffffffffu, s_hi,  o);
        sq_hi += __shfl_xor_sync(0xffffffffu, sq_hi, o);
    }
    const float mu_lo = s_lo * (1.f / D);
    const float mu_hi = s_hi * (1.f / D);
    const float rs_lo = rsqrtf(sq_lo * (1.f / D) - mu_lo * mu_lo + 1e-5f);
    const float rs_hi = rsqrtf(sq_hi * (1.f / D) - mu_hi * mu_hi + 1e-5f);

    float v1l = -1e30f, v2l = -1e30f, v3l = -1e30f;
    float v1h = -1e30f, v2h = -1e30f, v3h = -1e30f;
    int   i1l = 0, i2l = 0, i1h = 0, i2h = 0;
    #pragma unroll
    for (int nt = 0; nt < 8; nt++) {
        const int e0 = nt * 8 + 2 * tig;
        const float es0 = g_esum[e0], es1 = g_esum[e0 + 1];
        ins3(rs_lo * (acc[nt*4+0] - mu_lo * es0), e0,     v1l, i1l, v2l, i2l, v3l);
        ins3(rs_lo * (acc[nt*4+1] - mu_lo * es1), e0 + 1, v1l, i1l, v2l, i2l, v3l);
        ins3(rs_hi * (acc[nt*4+2] - mu_hi * es0), e0,     v1h, i1h, v2h, i2h, v3h);
        ins3(rs_hi * (acc[nt*4+3] - mu_hi * es1), e0 + 1, v1h, i1h, v2h, i2h, v3h);
    }
    #pragma unroll
    for (int o = 1; o <= 2; o <<= 1) {
        float ov1 = __shfl_xor_sync(0xffffffffu, v1l, o);
        float ov2 = __shfl_xor_sync(0xffffffffu, v2l, o);
        float ov3 = __shfl_xor_sync(0xffffffffu, v3l, o);
        int   oi1 = __shfl_xor_sync(0xffffffffu, i1l, o);
        int   oi2 = __shfl_xor_sync(0xffffffffu, i2l, o);
        ins3(ov1, oi1, v1l, i1l, v2l, i2l, v3l);
        ins3(ov2, oi2, v1l, i1l, v2l, i2l, v3l);
        if (ov3 > v3l) v3l = ov3;
        ov1 = __shfl_xor_sync(0xffffffffu, v1h, o);
        ov2 = __shfl_xor_sync(0xffffffffu, v2h, o);
        ov3 = __shfl_xor_sync(0xffffffffu, v3h, o);
        oi1 = __shfl_xor_sync(0xffffffffu, i1h, o);
        oi2 = __shfl_xor_sync(0xffffffffu, i2h, o);
        ins3(ov1, oi1, v1h, i1h, v2h, i2h, v3h);
        ins3(ov2, oi2, v1h, i1h, v2h, i2h, v3h);
        if (ov3 > v3h) v3h = ov3;
    }

    if (tig == 0) {
        const float invt = 1.f / 45.254833995939045f;   // 1/sqrt(2048)
        int t_lo = m0 + warp * 16 + g;
        int t_hi = t_lo + 8;
        float e2 = __expf((v2l - v1l) * invt);
        out[2 * t_lo + 0]        = (float)i1l;
        out[2 * t_lo + 1]        = (float)i2l;
        out[half + 2 * t_lo + 0] = 1.f / (1.f + e2);
        out[half + 2 * t_lo + 1] = e2 / (1.f + e2);
        e2 = __expf((v2h - v1h) * invt);
        out[2 * t_hi + 0]        = (float)i1h;
        out[2 * t_hi + 1]        = (float)i2h;
        out[half + 2 * t_hi + 0] = 1.f / (1.f + e2);
        out[half + 2 * t_hi + 1] = e2 / (1.f + e2);
        if (v1l - v2l < TAU || v2l - v3l < TAU)
            g_flag_list[atomicAdd(&g_flag_count, 1)] = t_lo;
        if (v1h - v2h < TAU || v2h - v3h < TAU)
            g_flag_list[atomicAdd(&g_flag_count, 1)] = t_hi;
    }
}

// ------------- kernel 3: fp32 exact fixup for near-tie tokens -------------
__global__ __launch_bounds__(256) void fixup_kernel(const float* __restrict__ x,
                                                    float* __restrict__ out, int half)
{
    __shared__ float xs[D];
    __shared__ float sims[NEXP];
    __shared__ float red[8];
    __shared__ float stats[2];
    const int tid = threadIdx.x;
    const int n = g_flag_count;
    for (int i = blockIdx.x; i < n; i += gridDim.x) {
        const int g = g_flag_list[i];
        const float4* xr = reinterpret_cast<const float4*>(x + (size_t)g * D);
        float4 a = xr[tid], b = xr[tid + 256];
        reinterpret_cast<float4*>(xs)[tid]       = a;
        reinterpret_cast<float4*>(xs)[tid + 256] = b;
        float s  = a.x + a.y + a.z + a.w + b.x + b.y + b.z + b.w;
        float sq = a.x*a.x + a.y*a.y + a.z*a.z + a.w*a.w
                 + b.x*b.x + b.y*b.y + b.z*b.z + b.w*b.w;
        s  = block_reduce256(s, red);
        sq = block_reduce256(sq, red);
        if (tid == 0) {
            float mu  = s * (1.f / D);
            float var = sq * (1.f / D) - mu * mu;
            stats[0] = mu;
            stats[1] = rsqrtf(var + 1e-5f);
        }
        __syncthreads();
        const float mu = stats[0], rstd = stats[1];
        const int e = tid >> 2, q = tid & 3;
        const float4* ea = reinterpret_cast<const float4*>(g_enorm + e * D + q * 512);
        const float4* xa = reinterpret_cast<const float4*>(xs + q * 512);
        float d = 0.f;
        #pragma unroll 4
        for (int k = 0; k < 128; k++) {
            float4 u = xa[k], v = ea[k];
            d += u.x * v.x + u.y * v.y + u.z * v.z + u.w * v.w;
        }
        d += __shfl_xor_sync(0xffffffffu, d, 1);
        d += __shfl_xor_sync(0xffffffffu, d, 2);
        if (q == 0) sims[e] = rstd * (d - mu * g_esum[e]);
        __syncthreads();
        if (tid == 0) {
            float v1 = -1e30f, v2 = -1e30f; int i1 = 0, i2 = 0;
            for (int ee = 0; ee < NEXP; ee++) {
                float v = sims[ee];
                if (v > v1)      { v2 = v1; i2 = i1; v1 = v; i1 = ee; }
                else if (v > v2) { v2 = v; i2 = ee; }
            }
            const float invt = 1.f / 45.254833995939045f;
            float e2 = __expf((v2 - v1) * invt);
            out[2 * g + 0]        = (float)i1;
            out[2 * g + 1]        = (float)i2;
            out[half + 2 * g + 0] = 1.f / (1.f + e2);
            out[half + 2 * g + 1] = e2 / (1.f + e2);
        }
        __syncthreads();
    }
}

// ------------- host -------------
extern "C" void kernel_launch(void* const* d_in, const int* in_sizes, int n_in,
                              void* d_out, int out_size) {
    const float* x   = (const float*)d_in[0];   // [4,4096,2048] fp32
    const float* emb = (const float*)d_in[1];   // [64,2048]     fp32
    float* out = (float*)d_out;
    const int half = out_size / 2;

    void* cnt_ptr = nullptr;
    cudaGetSymbolAddress(&cnt_ptr, g_flag_count);

    cudaFuncSetAttribute(gemm_kernel, cudaFuncAttributeMaxDynamicSharedMemorySize, SMEM_TOTAL);

    cudaMemsetAsync(cnt_ptr, 0, sizeof(int));
    normalize_experts<<<NEXP, 256>>>(emb);
    gemm_kernel<<<NTOK / TM, 256, SMEM_TOTAL>>>(x, out, half);
    fixup_kernel<<<256, 256>>>(x, out, half);
}

// round 4
// speedup vs baseline: 1.0175x; 1.0175x over previous
#include <cuda_runtime.h>
#include <math.h>
#include <stdint.h>

#define D        2048
#define NEXP     64
#define TM       128                      // tokens per CTA (4 warps x 32 rows)
#define KC       32
#define NCHUNK   (D / KC)                 // 64
#define STAGES   6
#define NTOK     16384
#define TAU      0.25f

#define APITCH   36                       // floats per A row: ldmatrix rows land in distinct banks
#define A_BYTES  (TM * APITCH * 4)        // 18432
#define B_BYTES  (KC * NEXP * 4)          // 8192 (fragment-ordered, no padding needed)
#define STAGE_BYTES (A_BYTES + B_BYTES)   // 26624
#define SMEM_TOTAL  (STAGES * STAGE_BYTES) // 159744

__device__ float g_enorm[NEXP * D];       // fp32 normalized experts (fixup path)
__device__ float g_bgl[D * NEXP];         // tf32 B in mma-fragment order
__device__ float g_esum[NEXP];
__device__ int   g_flag_list[NTOK];
__device__ int   g_flag_count;

__device__ __forceinline__ void cp_async16(uint32_t dst, const void* src) {
    asm volatile("cp.async.cg.shared.global [%0], [%1], 16;"
                 :: "r"(dst), "l"(src) : "memory");
}
__device__ __forceinline__ void ldmA(uint32_t& r0, uint32_t& r1, uint32_t& r2, uint32_t& r3,
                                     uint32_t addr) {
    asm volatile("ldmatrix.sync.aligned.m8n8.x4.shared.b16 {%0,%1,%2,%3}, [%4];"
                 : "=r"(r0), "=r"(r1), "=r"(r2), "=r"(r3) : "r"(addr));
}
__device__ __forceinline__ void mma_tf32(float* c, uint32_t a0, uint32_t a1, uint32_t a2,
                                         uint32_t a3, float b0, float b1) {
    asm volatile(
        "mma.sync.aligned.m16n8k8.row.col.f32.tf32.tf32.f32 "
        "{%0,%1,%2,%3}, {%4,%5,%6,%7}, {%8,%9}, {%0,%1,%2,%3};"
        : "+f"(c[0]), "+f"(c[1]), "+f"(c[2]), "+f"(c[3])
        : "r"(a0), "r"(a1), "r"(a2), "r"(a3),
          "r"(__float_as_uint(b0)), "r"(__float_as_uint(b1)));
}
__device__ __forceinline__ void ins3(float v, int e, float& v1, int& i1,
                                     float& v2, int& i2, float& v3) {
    if (v > v1)      { v3 = v2; v2 = v1; i2 = i1; v1 = v; i1 = e; }
    else if (v > v2) { v3 = v2; v2 = v; i2 = e; }
    else if (v > v3) { v3 = v; }
}

// B fragment-order store: consumer lane (g,tig) reads float4 j=(ks*4+ntp) as
// {b0(nt=2ntp), b1(nt=2ntp), b0(nt=2ntp+1), b1(nt=2ntp+1)}, lane-major.
__device__ __forceinline__ void bgl_store(int k, int e, float v) {
    int c = k >> 5, kk = k & 31;
    int ks = kk >> 3, kr = kk & 7, tg = kr & 3, hf = kr >> 2;
    int gg = e & 7, nt = e >> 3, ntp = nt >> 1, nto = nt & 1;
    int lane = gg * 4 + tg;
    g_bgl[c * 2048 + ((ks * 4 + ntp) * 32 + lane) * 4 + hf + 2 * nto] = v;
}

__device__ __forceinline__ float2 block_reduce256_2(float a, float b, float2* red) {
    int tid = threadIdx.x;
    __syncthreads();
    #pragma unroll
    for (int o = 16; o > 0; o >>= 1) {
        a += __shfl_xor_sync(0xffffffffu, a, o);
        b += __shfl_xor_sync(0xffffffffu, b, o);
    }
    if ((tid & 31) == 0) red[tid >> 5] = make_float2(a, b);
    __syncthreads();
    float2 r = (tid < 8) ? red[tid] : make_float2(0.f, 0.f);
    #pragma unroll
    for (int o = 4; o > 0; o >>= 1) {
        r.x += __shfl_xor_sync(0xffffffffu, r.x, o);
        r.y += __shfl_xor_sync(0xffffffffu, r.y, o);
    }
    if (tid == 0) red[0] = r;
    __syncthreads();
    return red[0];
}

// ------------- kernel 1: normalize experts -> g_enorm (fp32) + g_bgl (tf32, mma order) ----
__global__ __launch_bounds__(256) void normalize_experts(const float* __restrict__ emb) {
    __shared__ float2 red[8];
    const int e = blockIdx.x, tid = threadIdx.x;
    const float4* row = reinterpret_cast<const float4*>(emb + e * D);
    float4 v0 = row[tid];
    float4 v1 = row[tid + 256];
    float s  = v0.x + v0.y + v0.z + v0.w + v1.x + v1.y + v1.z + v1.w;
    float sq = v0.x*v0.x + v0.y*v0.y + v0.z*v0.z + v0.w*v0.w
             + v1.x*v1.x + v1.y*v1.y + v1.z*v1.z + v1.w*v1.w;
    float2 ssq = block_reduce256_2(s, sq, red);
    const float mu   = ssq.x * (1.f / D);
    const float var  = ssq.y * (1.f / D) - mu * mu;
    const float rstd = rsqrtf(var + 1e-5f);

    float nv[8];
    nv[0] = (v0.x-mu)*rstd; nv[1] = (v0.y-mu)*rstd; nv[2] = (v0.z-mu)*rstd; nv[3] = (v0.w-mu)*rstd;
    nv[4] = (v1.x-mu)*rstd; nv[5] = (v1.y-mu)*rstd; nv[6] = (v1.z-mu)*rstd; nv[7] = (v1.w-mu)*rstd;

    float4* o = reinterpret_cast<float4*>(g_enorm + e * D);
    o[tid]       = make_float4(nv[0], nv[1], nv[2], nv[3]);
    o[tid + 256] = make_float4(nv[4], nv[5], nv[6], nv[7]);

    float ls = 0.f;
    #pragma unroll
    for (int i = 0; i < 4; i++) {
        int k0 = tid * 4 + i;
        int k1 = 1024 + tid * 4 + i;
        uint32_t r0, r1;                          // pre-round B to tf32 (RNA)
        asm("cvt.rna.tf32.f32 %0, %1;" : "=r"(r0) : "f"(nv[i]));
        asm("cvt.rna.tf32.f32 %0, %1;" : "=r"(r1) : "f"(nv[4 + i]));
        bgl_store(k0, e, __uint_as_float(r0));
        bgl_store(k1, e, __uint_as_float(r1));
        ls += nv[i] + nv[4 + i];
    }
    float2 lz = block_reduce256_2(ls, 0.f, red);
    if (tid == 0) g_esum[e] = lz.x;
}

// ------------- kernel 2: tf32 mma GEMM (ldmatrix A, fragment-ordered B) + LN + top-2 -----
__global__ __launch_bounds__(128, 1) void gemm_kernel(const float* __restrict__ x,
                                                      float* __restrict__ out, int half)
{
    extern __shared__ __align__(128) char smem[];
    __shared__ float es_sh[NEXP];
    const uint32_t sb = (uint32_t)__cvta_generic_to_shared(smem);

    const int tid  = threadIdx.x;
    const int warp = tid >> 5;
    const int lane = tid & 31;
    const int g    = lane >> 2;
    const int tig  = lane & 3;
    const int m0   = blockIdx.x * TM;
    const int R    = warp * 32;

    if (tid < NEXP) es_sh[tid] = g_esum[tid];

    #define ISSUE_OPS(c) do {                                                   \
        int st_ = (c) % STAGES;                                                 \
        uint32_t base_ = sb + st_ * STAGE_BYTES;                                \
        _Pragma("unroll")                                                       \
        for (int i_ = 0; i_ < 8; i_++) {                                        \
            int idx_ = tid + i_ * 128;                                          \
            int row_ = idx_ >> 3, seg_ = idx_ & 7;                              \
            cp_async16(base_ + row_ * (APITCH * 4) + seg_ * 16,                 \
                       x + (size_t)(m0 + row_) * D + (c) * KC + seg_ * 4);      \
        }                                                                       \
        _Pragma("unroll")                                                       \
        for (int i_ = 0; i_ < 4; i_++) {                                        \
            int idx_ = tid + i_ * 128;                                          \
            cp_async16(base_ + A_BYTES + idx_ * 16, g_bgl + (c) * 2048 + idx_ * 4); \
        }                                                                       \
    } while (0)

    #pragma unroll
    for (int c = 0; c < STAGES - 1; c++) {
        ISSUE_OPS(c);
        asm volatile("cp.async.commit_group;" ::: "memory");
    }

    float acc[64];
    #pragma unroll
    for (int i = 0; i < 64; i++) acc[i] = 0.f;
    float s[4] = {0.f, 0.f, 0.f, 0.f}, sq[4] = {0.f, 0.f, 0.f, 0.f};

    // per-lane ldmatrix address pieces (row = base + (lane&15), col-half = lane>>4)
    const uint32_t aoff = (uint32_t)((R + (lane & 15)) * (APITCH * 4) + (lane >> 4) * 16);

    for (int c = 0; c < NCHUNK; c++) {
        asm volatile("cp.async.wait_group 4;" ::: "memory");
        __syncthreads();
        if (c + STAGES - 1 < NCHUNK) ISSUE_OPS(c + STAGES - 1);
        asm volatile("cp.async.commit_group;" ::: "memory");

        const uint32_t base = sb + (c % STAGES) * STAGE_BYTES;
        const uint32_t a0 = base + aoff;
        const uint32_t a1 = a0 + 16 * (APITCH * 4);
        const uint32_t bb = base + A_BYTES + lane * 16;

        #pragma unroll
        for (int ks = 0; ks < 4; ks++) {
            uint32_t f0, f1, f2, f3, h0, h1, h2, h3;
            ldmA(f0, f1, f2, f3, a0 + ks * 32);
            ldmA(h0, h1, h2, h3, a1 + ks * 32);
            {   // token stats from fragments (rows R+g, R+8+g, R+16+g, R+24+g)
                float u0 = __uint_as_float(f0), u1 = __uint_as_float(f1);
                float u2 = __uint_as_float(f2), u3 = __uint_as_float(f3);
                float w0 = __uint_as_float(h0), w1 = __uint_as_float(h1);
                float w2 = __uint_as_float(h2), w3 = __uint_as_float(h3);
                s[0] += u0 + u2;  sq[0] += u0 * u0 + u2 * u2;
                s[1] += u1 + u3;  sq[1] += u1 * u1 + u3 * u3;
                s[2] += w0 + w2;  sq[2] += w0 * w0 + w2 * w2;
                s[3] += w1 + w3;  sq[3] += w1 * w1 + w3 * w3;
            }
            #pragma unroll
            for (int p = 0; p < 4; p++) {
                float bx, by, bz, bw;
                asm volatile("ld.shared.v4.f32 {%0,%1,%2,%3}, [%4];"
                             : "=f"(bx), "=f"(by), "=f"(bz), "=f"(bw)
                             : "r"(bb + (ks * 4 + p) * 512));
                mma_tf32(acc + (2 * p) * 4,     f0, f1, f2, f3, bx, by);
                mma_tf32(acc + (2 * p + 1) * 4, f0, f1, f2, f3, bz, bw);
                mma_tf32(acc + (8 + 2 * p) * 4,     h0, h1, h2, h3, bx, by);
                mma_tf32(acc + (8 + 2 * p + 1) * 4, h0, h1, h2, h3, bz, bw);
            }
        }
    }
    asm volatile("cp.async.wait_all;" ::: "memory");

    // stats: reduce over the 4 tig lanes
    #pragma unroll
    for (int o = 1; o <= 2; o <<= 1) {
        #pragma unroll
        for (int j = 0; j < 4; j++) {
            s[j]  += __shfl_xor_sync(0xffffffffu, s[j],  o);
            sq[j] += __shfl_xor_sync(0xffffffffu, sq[j], o);
        }
    }

    const float invt = 1.f / 45.254833995939045f;   // 1/sqrt(2048)
    #pragma unroll
    for (int j = 0; j < 4; j++) {
        const float mu = s[j] * (1.f / D);
        const float rs = rsqrtf(sq[j] * (1.f / D) - mu * mu + 1e-5f);
        float v1 = -1e30f, v2 = -1e30f, v3 = -1e30f;
        int   i1 = 0, i2 = 0;
        #pragma unroll
        for (int nt = 0; nt < 8; nt++) {
            const int e0 = nt * 8 + 2 * tig;
            const float es0 = es_sh[e0], es1 = es_sh[e0 + 1];
            const float c0 = acc[((j >> 1) * 8 + nt) * 4 + (j & 1) * 2 + 0];
            const float c1 = acc[((j >> 1) * 8 + nt) * 4 + (j & 1) * 2 + 1];
            ins3(rs * (c0 - mu * es0), e0,     v1, i1, v2, i2, v3);
            ins3(rs * (c1 - mu * es1), e0 + 1, v1, i1, v2, i2, v3);
        }
        #pragma unroll
        for (int o = 1; o <= 2; o <<= 1) {
            float ov1 = __shfl_xor_sync(0xffffffffu, v1, o);
            float ov2 = __shfl_xor_sync(0xffffffffu, v2, o);
            float ov3 = __shfl_xor_sync(0xffffffffu, v3, o);
            int   oi1 = __shfl_xor_sync(0xffffffffu, i1, o);
            int   oi2 = __shfl_xor_sync(0xffffffffu, i2, o);
            ins3(ov1, oi1, v1, i1, v2, i2, v3);
            ins3(ov2, oi2, v1, i1, v2, i2, v3);
            if (ov3 > v3) v3 = ov3;
        }
        if (tig == 0) {
            const int t = m0 + R + g + j * 8;
            float e2 = __expf((v2 - v1) * invt);
            out[2 * t + 0]        = (float)i1;
            out[2 * t + 1]        = (float)i2;
            out[half + 2 * t + 0] = 1.f / (1.f + e2);
            out[half + 2 * t + 1] = e2 / (1.f + e2);
            if (v1 - v2 < TAU || v2 - v3 < TAU)
                g_flag_list[atomicAdd(&g_flag_count, 1)] = t;
        }
    }
}

// ------------- kernel 3: fp32 exact fixup for near-tie tokens -------------
__global__ __launch_bounds__(256) void fixup_kernel(const float* __restrict__ x,
                                                    float* __restrict__ out, int half)
{
    __shared__ float xs[D];
    __shared__ float sims[NEXP];
    __shared__ float2 red[8];
    __shared__ float stats[2];
    const int tid = threadIdx.x;
    const int n = g_flag_count;
    for (int i = blockIdx.x; i < n; i += gridDim.x) {
        const int g = g_flag_list[i];
        const float4* xr = reinterpret_cast<const float4*>(x + (size_t)g * D);
        float4 a = xr[tid], b = xr[tid + 256];
        reinterpret_cast<float4*>(xs)[tid]       = a;
        reinterpret_cast<float4*>(xs)[tid + 256] = b;
        float s  = a.x + a.y + a.z + a.w + b.x + b.y + b.z + b.w;
        float sq = a.x*a.x + a.y*a.y + a.z*a.z + a.w*a.w
                 + b.x*b.x + b.y*b.y + b.z*b.z + b.w*b.w;
        float2 ssq = block_reduce256_2(s, sq, red);
        if (tid == 0) {
            float mu  = ssq.x * (1.f / D);
            float var = ssq.y * (1.f / D) - mu * mu;
            stats[0] = mu;
            stats[1] = rsqrtf(var + 1e-5f);
        }
        __syncthreads();
        const float mu = stats[0], rstd = stats[1];
        const int e = tid >> 2, q = tid & 3;
        const float4* ea = reinterpret_cast<const float4*>(g_enorm + e * D + q * 512);
        const float4* xa = reinterpret_cast<const float4*>(xs + q * 512);
        float d = 0.f;
        #pragma unroll 4
        for (int k = 0; k < 128; k++) {
            float4 u = xa[k], v = ea[k];
            d += u.x * v.x + u.y * v.y + u.z * v.z + u.w * v.w;
        }
        d += __shfl_xor_sync(0xffffffffu, d, 1);
        d += __shfl_xor_sync(0xffffffffu, d, 2);
        if (q == 0) sims[e] = rstd * (d - mu * g_esum[e]);
        __syncthreads();
        if (tid == 0) {
            float v1 = -1e30f, v2 = -1e30f; int i1 = 0, i2 = 0;
            for (int ee = 0; ee < NEXP; ee++) {
                float v = sims[ee];
                if (v > v1)      { v2 = v1; i2 = i1; v1 = v; i1 = ee; }
                else if (v > v2) { v2 = v; i2 = ee; }
            }
            const float invt = 1.f / 45.254833995939045f;
            float e2 = __expf((v2 - v1) * invt);
            out[2 * g + 0]        = (float)i1;
            out[2 * g + 1]        = (float)i2;
            out[half + 2 * g + 0] = 1.f / (1.f + e2);
            out[half + 2 * g + 1] = e2 / (1.f + e2);
        }
        __syncthreads();
    }
}

// ------------- host -------------
extern "C" void kernel_launch(void* const* d_in, const int* in_sizes, int n_in,
                              void* d_out, int out_size) {
    const float* x   = (const float*)d_in[0];   // [4,4096,2048] fp32
    const float* emb = (const float*)d_in[1];   // [64,2048]     fp32
    float* out = (float*)d_out;
    const int half = out_size / 2;

    void* cnt_ptr = nullptr;
    cudaGetSymbolAddress(&cnt_ptr, g_flag_count);

    cudaFuncSetAttribute(gemm_kernel, cudaFuncAttributeMaxDynamicSharedMemorySize, SMEM_TOTAL);

    cudaMemsetAsync(cnt_ptr, 0, sizeof(int));
    normalize_experts<<<NEXP, 256>>>(emb);
    gemm_kernel<<<NTOK / TM, 128, SMEM_TOTAL>>>(x, out, half);
    fixup_kernel<<<256, 256>>>(x, out, half);
}